// round 1
// baseline (speedup 1.0000x reference)
#include <cuda_runtime.h>
#include <cstdint>

// ---------------------------------------------------------------------------
// GeometricPositionalFingerprinter
// Input : pentachora [V, 5, 128] f32  (V = in_sizes[0]/640)
// Output: cantor fingerprint [V] f32
//
// Layout: 4 lanes per pentachoron (8 pentachora per warp).
// Each lane streams 8 float4 chunks per vertex, accumulating:
//   - 15 pairwise dot products (full 5x5 upper gram incl. diagonal)
//   - 5 squared distances to the centroid (explicit diff, matches reference
//     numerics; gram-derived form has a cancellation that risks Cantor flips)
// 2-step XOR butterfly reduces within the 4-lane group; all 4 lanes then
// redundantly compute the scalar epilogue (free under SIMT), lane 0 stores.
// ---------------------------------------------------------------------------

__device__ __forceinline__ float sigmoid_pos(float x) {
    // x >= 0 always in this kernel. Accurate ~2 ulp regardless of fast-math:
    // hand-rolled Cody-Waite exp(-x) + correctly-rounded divide.
    if (x > 18.0f) return 1.0f;  // exp(-x) < 2^-25 -> 1/(1+e) rounds to 1.0f
    float t = -x;
    float kf = rintf(t * 1.4426950408889634f);
    float r = fmaf(-kf, 0.693145751953125f, t);       // ln2_hi
    r = fmaf(-kf, 1.428606765330187e-06f, r);         // ln2_lo
    // e^r, r in [-0.347, 0.347], degree-6 Taylor (rel err ~1.2e-7)
    float p = fmaf(r, 1.38888889e-3f, 8.33333333e-3f);
    p = fmaf(r, p, 4.16666667e-2f);
    p = fmaf(r, p, 1.66666667e-1f);
    p = fmaf(r, p, 0.5f);
    p = fmaf(r, p, 1.0f);
    p = fmaf(r, p, 1.0f);
    int ki = (int)kf;                                  // ki in [-26, 0]
    float scale = __int_as_float((ki + 127) << 23);    // 2^ki (no denormal risk)
    float e = p * scale;
    return __fdiv_rn(1.0f, __fadd_rn(1.0f, e));
}

__global__ void __launch_bounds__(256)
gpf_kernel(const float* __restrict__ pent, float* __restrict__ out, int V)
{
    int tid = blockIdx.x * 256 + threadIdx.x;
    int g = tid >> 2;        // pentachoron index
    int s = tid & 3;         // sublane within 4-lane group
    if (g >= V) return;

    // Each pentachoron = 640 floats = 160 float4. Lane s handles float4
    // columns {s, s+4, ..., s+28} of each 32-float4 vertex row.
    const float4* __restrict__ base =
        reinterpret_cast<const float4*>(pent) + (size_t)g * 160 + s;

    float acc[15];  // gram upper triangle incl diagonal, row-major (i<=j)
    float cd[5];    // squared distance to centroid per vertex
#pragma unroll
    for (int i = 0; i < 15; ++i) acc[i] = 0.0f;
#pragma unroll
    for (int v = 0; v < 5; ++v) cd[v] = 0.0f;

#pragma unroll
    for (int c = 0; c < 8; ++c) {
        float4 a[5];
#pragma unroll
        for (int v = 0; v < 5; ++v) a[v] = base[v * 32 + c * 4];

        // centroid chunk (mul by 0.2f; error immaterial through the diff path)
        float cx = (((a[0].x + a[1].x) + (a[2].x + a[3].x)) + a[4].x) * 0.2f;
        float cy = (((a[0].y + a[1].y) + (a[2].y + a[3].y)) + a[4].y) * 0.2f;
        float cz = (((a[0].z + a[1].z) + (a[2].z + a[3].z)) + a[4].z) * 0.2f;
        float cw = (((a[0].w + a[1].w) + (a[2].w + a[3].w)) + a[4].w) * 0.2f;

        int k = 0;
#pragma unroll
        for (int i = 0; i < 5; ++i) {
#pragma unroll
            for (int j = i; j < 5; ++j) {
                float t = acc[k];
                t = fmaf(a[i].x, a[j].x, t);
                t = fmaf(a[i].y, a[j].y, t);
                t = fmaf(a[i].z, a[j].z, t);
                t = fmaf(a[i].w, a[j].w, t);
                acc[k] = t;
                ++k;
            }
        }
#pragma unroll
        for (int v = 0; v < 5; ++v) {
            float dx = a[v].x - cx;
            float dy = a[v].y - cy;
            float dz = a[v].z - cz;
            float dw = a[v].w - cw;
            float t = cd[v];
            t = fmaf(dx, dx, t);
            t = fmaf(dy, dy, t);
            t = fmaf(dz, dz, t);
            t = fmaf(dw, dw, t);
            cd[v] = t;
        }
    }

    // Butterfly reduce across the 4-lane group (all lanes end with same value)
#pragma unroll
    for (int i = 0; i < 15; ++i) {
        acc[i] += __shfl_xor_sync(0xffffffffu, acc[i], 1);
        acc[i] += __shfl_xor_sync(0xffffffffu, acc[i], 2);
    }
#pragma unroll
    for (int v = 0; v < 5; ++v) {
        cd[v] += __shfl_xor_sync(0xffffffffu, cd[v], 1);
        cd[v] += __shfl_xor_sync(0xffffffffu, cd[v], 2);
    }

    // Unpack full symmetric gram
    float gm[5][5];
    {
        int k = 0;
#pragma unroll
        for (int i = 0; i < 5; ++i)
#pragma unroll
            for (int j = i; j < 5; ++j) {
                gm[i][j] = acc[k];
                gm[j][i] = acc[k];
                ++k;
            }
    }

    // --- Edge statistics (triu order matches np.triu_indices(5, k=1)) ---
    float e[10];
    {
        int m = 0;
#pragma unroll
        for (int i = 0; i < 5; ++i)
#pragma unroll
            for (int j = i + 1; j < 5; ++j) {
                float ds = __fsub_rn(__fadd_rn(gm[i][i], gm[j][j]),
                                     __fmul_rn(2.0f, gm[i][j]));
                ds = fmaxf(ds, 0.0f);
                e[m++] = __fsqrt_rn(ds);
            }
    }
    float esum = 0.0f;
#pragma unroll
    for (int i = 0; i < 10; ++i) esum = __fadd_rn(esum, e[i]);
    float mean_edge = __fdiv_rn(esum, 10.0f);
    float ess = 0.0f;
#pragma unroll
    for (int i = 0; i < 10; ++i) {
        float d = __fsub_rn(e[i], mean_edge);
        ess = fmaf(d, d, ess);
    }
    float std_edge = __fsqrt_rn(__fdiv_rn(ess, 9.0f));   // ddof=1
    float ratio = __fdiv_rn(std_edge, __fadd_rn(mean_edge, 1e-6f));

    // --- Vertex spread (ddof=1 std of distances to centroid) ---
    float dc[5];
    float csum = 0.0f;
#pragma unroll
    for (int v = 0; v < 5; ++v) {
        dc[v] = __fsqrt_rn(cd[v]);
        csum = __fadd_rn(csum, dc[v]);
    }
    float cmean = __fdiv_rn(csum, 5.0f);
    float css = 0.0f;
#pragma unroll
    for (int v = 0; v < 5; ++v) {
        float d = __fsub_rn(dc[v], cmean);
        css = fmaf(d, d, css);
    }
    float spread = __fsqrt_rn(__fdiv_rn(css, 4.0f));

    // --- Volume via 4x4 edge-vector Gram determinant ---
    // G[i][j] = (p_{i+1}-p_0)·(p_{j+1}-p_0);  vol^2 = det(G)/(4!)^2 = det/576
    // Mathematically identical to -det(CM)/9216. sigmoid(10*vol) saturates to
    // exactly 1.0f (vol ~ O(1000) for gaussian data), so fp32 det rounding is
    // invisible in the output.
    float G[4][4];
#pragma unroll
    for (int i = 0; i < 4; ++i)
#pragma unroll
        for (int j = 0; j < 4; ++j)
            G[i][j] = (gm[i + 1][j + 1] - gm[0][i + 1]) - (gm[0][j + 1] - gm[0][0]);

    float d2233 = G[2][2] * G[3][3] - G[2][3] * G[3][2];
    float d2133 = G[2][1] * G[3][3] - G[2][3] * G[3][1];
    float d2132 = G[2][1] * G[3][2] - G[2][2] * G[3][1];
    float d2033 = G[2][0] * G[3][3] - G[2][3] * G[3][0];
    float d2032 = G[2][0] * G[3][2] - G[2][2] * G[3][0];
    float d2031 = G[2][0] * G[3][1] - G[2][1] * G[3][0];
    float c0 = G[1][1] * d2233 - G[1][2] * d2133 + G[1][3] * d2132;
    float c1 = G[1][0] * d2233 - G[1][2] * d2033 + G[1][3] * d2032;
    float c2 = G[1][0] * d2133 - G[1][1] * d2033 + G[1][3] * d2031;
    float c3 = G[1][0] * d2132 - G[1][1] * d2032 + G[1][2] * d2031;
    float det = G[0][0] * c0 - G[0][1] * c1 + G[0][2] * c2 - G[0][3] * c3;
    float vol = __fsqrt_rn(fmaxf(__fdiv_rn(det, 576.0f), 0.0f));

    // --- Seed: match reference op order ((a*0.4 + b*0.3) + c*0.3), no FMA ---
    float s1 = sigmoid_pos(__fmul_rn(vol, 10.0f));
    float s2 = sigmoid_pos(ratio);
    float s3 = sigmoid_pos(spread);
    float seed = __fadd_rn(__fadd_rn(__fmul_rn(s1, 0.4f), __fmul_rn(s2, 0.3f)),
                           __fmul_rn(s3, 0.3f));

    float x = fminf(fmaxf(seed, 1e-6f), 0.999999f);

    // --- Ternary Cantor digits (bit-identical fp op sequence vs reference) ---
    float cantor = 0.0f;
    float factor = 0.5f;
#pragma unroll
    for (int it = 0; it < 8; ++it) {
        float xs = __fmul_rn(x, 3.0f);
        int d = (int)xs;                       // trunc == astype(int32)
        x = __fsub_rn(xs, (float)d);
        if (d == 2) cantor = __fadd_rn(cantor, factor);
        factor *= 0.5f;
    }

    if (s == 0) out[g] = fminf(fmaxf(cantor, 0.0f), 1.0f);
}

extern "C" void kernel_launch(void* const* d_in, const int* in_sizes, int n_in,
                              void* d_out, int out_size)
{
    const float* p = (const float*)d_in[0];
    float* out = (float*)d_out;
    int V = in_sizes[0] / 640;                 // [V, 5, 128]
    long long total = (long long)V * 4;        // 4 lanes per pentachoron
    int threads = 256;
    int blocks = (int)((total + threads - 1) / threads);
    gpf_kernel<<<blocks, threads>>>(p, out, V);
}